// round 5
// baseline (speedup 1.0000x reference)
#include <cuda_runtime.h>
#include <cstdint>

namespace {

constexpr int NTH  = 256;
constexpr int NBLK = 4096;
constexpr int ROWS = 1024;

typedef unsigned long long u64;

// packed f32x2 helpers (sm_103a; PTX-only, ptxas never auto-fuses)
__device__ __forceinline__ u64 pk2(float lo, float hi) {
    u64 d; asm("mov.b64 %0, {%1, %2};" : "=l"(d) : "f"(lo), "f"(hi)); return d;
}
__device__ __forceinline__ void upk2(float& lo, float& hi, u64 p) {
    asm("mov.b64 {%0, %1}, %2;" : "=f"(lo), "=f"(hi) : "l"(p));
}
__device__ __forceinline__ u64 fma2(u64 a, u64 b, u64 c) {
    u64 d; asm("fma.rn.f32x2 %0, %1, %2, %3;" : "=l"(d) : "l"(a), "l"(b), "l"(c)); return d;
}
__device__ __forceinline__ u64 add2(u64 a, u64 b) {
    u64 d; asm("add.rn.f32x2 %0, %1, %2;" : "=l"(d) : "l"(a), "l"(b)); return d;
}

__device__ __forceinline__ float cnrm(const float4 c) {
    return fmaf(c.w, c.w, fmaf(c.z, c.z, fmaf(c.y, c.y, c.x * c.x)));
}

__global__ __launch_bounds__(NTH, 6)
void viterbi_kernel(const float* __restrict__ array,
                    const float* __restrict__ codebook,
                    float* __restrict__ out,
                    int out_size)
{
    __shared__ float alpha[2][1024];            // ping-pong alpha
    __shared__ ulonglong2 xsd[64][2];           // -2*x, components duplicated as pairs (32B/step)
    __shared__ unsigned int bpsm[4][NTH];       // 2-bit bp, packed 16 steps per word
    __shared__ int   path[64];
    __shared__ float redv[8];
    __shared__ int   redi[8];

    const int k  = threadIdx.x;                 // state group: owns states 4k..4k+3
    const int b  = blockIdx.x;
    const int br = b >> 6;
    const int bc = b & 63;

    // ---- load this block's 256 elements, pre-scaled by -2, duplicated pairs ----
    {
        int r = k >> 4, cc = k & 15;
        float v = -2.0f * array[(br * 16 + r) * ROWS + (bc * 16 + cc)];
        // element k: step t = k>>2, component = k&3 -> u64 slot (k&3): pairs (lo,hi) per 16B
        u64 p = pk2(v, v);
        reinterpret_cast<u64*>(&xsd[k >> 2][0])[k & 3] = p;
    }

    // ---- codebook rows 4k..4k+3 -> packed pair registers ----
    const float4* cb4 = reinterpret_cast<const float4*>(codebook);
    float4 o0 = __ldg(cb4 + 4 * k + 0);
    float4 o1 = __ldg(cb4 + 4 * k + 1);
    float4 o2 = __ldg(cb4 + 4 * k + 2);
    float4 o3 = __ldg(cb4 + 4 * k + 3);
    u64 cx01 = pk2(o0.x, o1.x), cy01 = pk2(o0.y, o1.y), cz01 = pk2(o0.z, o1.z), cw01 = pk2(o0.w, o1.w);
    u64 cx23 = pk2(o2.x, o3.x), cy23 = pk2(o2.y, o3.y), cz23 = pk2(o2.z, o3.z), cw23 = pk2(o2.w, o3.w);
    u64 cn01 = pk2(cnrm(o0), cnrm(o1));
    u64 cn23 = pk2(cnrm(o2), cnrm(o3));

    __syncthreads();

    // ---- alpha_0 = cost(x0) (free initial state) -> alpha[0] ----
    u64 v01, v23;
    {
        ulonglong2 xa = xsd[0][0], xb = xsd[0][1];
        v01 = fma2(cw01, xb.y, fma2(cz01, xb.x, fma2(cy01, xa.y, fma2(cx01, xa.x, cn01))));
        v23 = fma2(cw23, xb.y, fma2(cz23, xb.x, fma2(cy23, xa.y, fma2(cx23, xa.x, cn23))));
        *reinterpret_cast<ulonglong2*>(&alpha[0][4 * k]) = make_ulonglong2(v01, v23);
    }
    __syncthreads();

    // ---- forward recursion: 63 steps ----
    unsigned int cw = 0;                        // 2-bit backpointers, 16 steps per word
#pragma unroll 2
    for (int t = 1; t < 64; ++t) {
        const float* ap = alpha[(t + 1) & 1];
        float a0 = ap[k];
        float a1 = ap[k + 256];
        float a2 = ap[k + 512];
        float a3 = ap[k + 768];
        float m = a0; int j = 0;                // strict < -> first-occurrence argmin
        if (a1 < m) { m = a1; j = 1; }
        if (a2 < m) { m = a2; j = 2; }
        if (a3 < m) { m = a3; j = 3; }
        cw |= (unsigned int)j << (2 * (t & 15));
        if ((t & 15) == 15) { bpsm[t >> 4][k] = cw; cw = 0; }

        ulonglong2 xa = xsd[t][0], xb = xsd[t][1];
        u64 mm = pk2(m, m);
        u64 c01 = fma2(cw01, xb.y, fma2(cz01, xb.x, fma2(cy01, xa.y, fma2(cx01, xa.x, cn01))));
        u64 c23 = fma2(cw23, xb.y, fma2(cz23, xb.x, fma2(cy23, xa.y, fma2(cx23, xa.x, cn23))));
        v01 = add2(mm, c01);
        v23 = add2(mm, c23);
        *reinterpret_cast<ulonglong2*>(&alpha[t & 1][4 * k]) = make_ulonglong2(v01, v23);
        __syncthreads();
    }

    // ---- final argmin over 1024 states (first-occurrence semantics) ----
    float v0, v1, v2, v3;
    upk2(v0, v1, v01);
    upk2(v2, v3, v23);
    float bm = v0; int bi = 4 * k;
    if (v1 < bm) { bm = v1; bi = 4 * k + 1; }
    if (v2 < bm) { bm = v2; bi = 4 * k + 2; }
    if (v3 < bm) { bm = v3; bi = 4 * k + 3; }
#pragma unroll
    for (int off = 16; off; off >>= 1) {
        float om = __shfl_down_sync(0xffffffffu, bm, off);
        int   oi = __shfl_down_sync(0xffffffffu, bi, off);
        if (om < bm || (om == bm && oi < bi)) { bm = om; bi = oi; }
    }
    if ((k & 31) == 0) { redv[k >> 5] = bm; redi[k >> 5] = bi; }
    __syncthreads();

    // ---- backtrack (single thread; hidden by co-resident CTAs) ----
    if (k == 0) {
        float m = redv[0]; int s = redi[0];
#pragma unroll
        for (int w = 1; w < 8; ++w) {
            if (redv[w] < m || (redv[w] == m && redi[w] < s)) { m = redv[w]; s = redi[w]; }
        }
        path[63] = s;
        for (int t = 63; t >= 1; --t) {
            int g = s >> 2;
            int j = (bpsm[t >> 4][g] >> (2 * (t & 15))) & 3;
            s = g + (j << 8);                   // prev = (s>>2) + j*HI, HI = 256
            path[t - 1] = s;
        }
    }
    __syncthreads();

    // ---- emit: rec (exact codebook gather) + states ----
    if (k < 64) {
        int t = k;
        int s = path[t];
        float4 val = __ldg(cb4 + s);
        int row = br * 16 + (t >> 2);
        int col = bc * 16 + ((t & 3) << 2);
        reinterpret_cast<float4*>(out + row * ROWS + col)[0] = val;
        int sidx = ROWS * ROWS + b * 64 + t;
        if (sidx < out_size) out[sidx] = (float)s;
    }
}

} // namespace

extern "C" void kernel_launch(void* const* d_in, const int* in_sizes, int n_in,
                              void* d_out, int out_size) {
    const float* array    = (const float*)d_in[0];
    const float* codebook = (const float*)d_in[1];
    (void)in_sizes; (void)n_in;
    float* out = (float*)d_out;
    viterbi_kernel<<<NBLK, NTH>>>(array, codebook, out, out_size);
}

// round 6
// speedup vs baseline: 1.1948x; 1.1948x over previous
#include <cuda_runtime.h>
#include <cstdint>

namespace {

constexpr int NTH  = 256;
constexpr int NCTA = 2048;   // each CTA handles 2 data blocks
constexpr int ROWS = 1024;

// cost chain: cn + cb.x*x.x + ... where x is pre-scaled by -2 (|x|^2 term dropped:
// constant across states per step, cannot change any argmin)
__device__ __forceinline__ float costf(const float4 cb, float cn, const float4 x) {
    return fmaf(cb.w, x.w, fmaf(cb.z, x.z, fmaf(cb.y, x.y, fmaf(cb.x, x.x, cn))));
}
__device__ __forceinline__ float cnrm(const float4 c) {
    return fmaf(c.w, c.w, fmaf(c.z, c.z, fmaf(c.y, c.y, c.x * c.x)));
}

__global__ __launch_bounds__(NTH, 5)
void viterbi_kernel(const float* __restrict__ array,
                    const float* __restrict__ codebook,
                    float* __restrict__ out,
                    int out_size)
{
    __shared__ float alphaA[2][1024];
    __shared__ float alphaB[2][1024];
    __shared__ float4 xsA[64];
    __shared__ float4 xsB[64];
    __shared__ unsigned char bp[64][NTH];   // jA in bits[1:0], jB in bits[3:2]
    __shared__ int   pathA[64], pathB[64];
    __shared__ float redvA[8], redvB[8];
    __shared__ int   rediA[8], rediB[8];

    const int k  = threadIdx.x;             // state group: owns states 4k..4k+3
    const int bA = 2 * blockIdx.x;
    const int bB = bA + 1;
    const int brA = bA >> 6, bcA = bA & 63;
    const int brB = bB >> 6, bcB = bB & 63;

    // ---- load both blocks' elements, pre-scaled by -2 ----
    {
        int r = k >> 4, cc = k & 15;
        float vA = array[(brA * 16 + r) * ROWS + (bcA * 16 + cc)];
        float vB = array[(brB * 16 + r) * ROWS + (bcB * 16 + cc)];
        reinterpret_cast<float*>(xsA)[k] = -2.0f * vA;
        reinterpret_cast<float*>(xsB)[k] = -2.0f * vB;
    }

    // ---- codebook rows 4k..4k+3 in registers (shared by both chains) ----
    const float4* cb4 = reinterpret_cast<const float4*>(codebook);
    float4 o0 = __ldg(cb4 + 4 * k + 0);
    float4 o1 = __ldg(cb4 + 4 * k + 1);
    float4 o2 = __ldg(cb4 + 4 * k + 2);
    float4 o3 = __ldg(cb4 + 4 * k + 3);
    float cn0 = cnrm(o0), cn1 = cnrm(o1), cn2 = cnrm(o2), cn3 = cnrm(o3);

    __syncthreads();

    // ---- alpha_0 = cost(x0) for both blocks ----
    float vA0, vA1, vA2, vA3, vB0, vB1, vB2, vB3;
    {
        float4 xA = xsA[0], xB = xsB[0];
        vA0 = costf(o0, cn0, xA); vA1 = costf(o1, cn1, xA);
        vA2 = costf(o2, cn2, xA); vA3 = costf(o3, cn3, xA);
        vB0 = costf(o0, cn0, xB); vB1 = costf(o1, cn1, xB);
        vB2 = costf(o2, cn2, xB); vB3 = costf(o3, cn3, xB);
        *reinterpret_cast<float4*>(&alphaA[0][4 * k]) = make_float4(vA0, vA1, vA2, vA3);
        *reinterpret_cast<float4*>(&alphaB[0][4 * k]) = make_float4(vB0, vB1, vB2, vB3);
    }
    __syncthreads();

    // ---- forward recursion: 63 steps, two independent chains interleaved ----
#pragma unroll 2
    for (int t = 1; t < 64; ++t) {
        const float* apA = alphaA[(t + 1) & 1];
        const float* apB = alphaB[(t + 1) & 1];
        float aA0 = apA[k], aA1 = apA[k + 256], aA2 = apA[k + 512], aA3 = apA[k + 768];
        float aB0 = apB[k], aB1 = apB[k + 256], aB2 = apB[k + 512], aB3 = apB[k + 768];

        float mA = aA0; int jA = 0;          // strict < -> first-occurrence argmin
        if (aA1 < mA) { mA = aA1; jA = 1; }
        if (aA2 < mA) { mA = aA2; jA = 2; }
        if (aA3 < mA) { mA = aA3; jA = 3; }
        float mB = aB0; int jB = 0;
        if (aB1 < mB) { mB = aB1; jB = 1; }
        if (aB2 < mB) { mB = aB2; jB = 2; }
        if (aB3 < mB) { mB = aB3; jB = 3; }
        bp[t][k] = (unsigned char)(jA | (jB << 2));

        float4 xA = xsA[t], xB = xsB[t];
        vA0 = mA + costf(o0, cn0, xA); vA1 = mA + costf(o1, cn1, xA);
        vA2 = mA + costf(o2, cn2, xA); vA3 = mA + costf(o3, cn3, xA);
        vB0 = mB + costf(o0, cn0, xB); vB1 = mB + costf(o1, cn1, xB);
        vB2 = mB + costf(o2, cn2, xB); vB3 = mB + costf(o3, cn3, xB);
        *reinterpret_cast<float4*>(&alphaA[t & 1][4 * k]) = make_float4(vA0, vA1, vA2, vA3);
        *reinterpret_cast<float4*>(&alphaB[t & 1][4 * k]) = make_float4(vB0, vB1, vB2, vB3);
        __syncthreads();
    }

    // ---- final argmin over 1024 states for both blocks (first-occurrence) ----
    {
        float bm = vA0; int bi = 4 * k;
        if (vA1 < bm) { bm = vA1; bi = 4 * k + 1; }
        if (vA2 < bm) { bm = vA2; bi = 4 * k + 2; }
        if (vA3 < bm) { bm = vA3; bi = 4 * k + 3; }
        float cm = vB0; int ci = 4 * k;
        if (vB1 < cm) { cm = vB1; ci = 4 * k + 1; }
        if (vB2 < cm) { cm = vB2; ci = 4 * k + 2; }
        if (vB3 < cm) { cm = vB3; ci = 4 * k + 3; }
#pragma unroll
        for (int off = 16; off; off >>= 1) {
            float om = __shfl_down_sync(0xffffffffu, bm, off);
            int   oi = __shfl_down_sync(0xffffffffu, bi, off);
            if (om < bm || (om == bm && oi < bi)) { bm = om; bi = oi; }
            float pm = __shfl_down_sync(0xffffffffu, cm, off);
            int   pi = __shfl_down_sync(0xffffffffu, ci, off);
            if (pm < cm || (pm == cm && pi < ci)) { cm = pm; ci = pi; }
        }
        if ((k & 31) == 0) {
            redvA[k >> 5] = bm; rediA[k >> 5] = bi;
            redvB[k >> 5] = cm; rediB[k >> 5] = ci;
        }
    }
    __syncthreads();

    // ---- backtrack: thread 0 does A, thread 32 does B (parallel warps) ----
    if (k == 0) {
        float m = redvA[0]; int s = rediA[0];
#pragma unroll
        for (int w = 1; w < 8; ++w)
            if (redvA[w] < m || (redvA[w] == m && rediA[w] < s)) { m = redvA[w]; s = rediA[w]; }
        pathA[63] = s;
        for (int t = 63; t >= 1; --t) {
            int g = s >> 2;
            int j = bp[t][g] & 3;
            s = g + (j << 8);
            pathA[t - 1] = s;
        }
    }
    if (k == 32) {
        float m = redvB[0]; int s = rediB[0];
#pragma unroll
        for (int w = 1; w < 8; ++w)
            if (redvB[w] < m || (redvB[w] == m && rediB[w] < s)) { m = redvB[w]; s = rediB[w]; }
        pathB[63] = s;
        for (int t = 63; t >= 1; --t) {
            int g = s >> 2;
            int j = (bp[t][g] >> 2) & 3;
            s = g + (j << 8);
            pathB[t - 1] = s;
        }
    }
    __syncthreads();

    // ---- emit: rec (exact codebook gather) + states, both blocks ----
    if (k < 128) {
        int t = k & 63;
        bool isB = k >= 64;
        int s = isB ? pathB[t] : pathA[t];
        int bb = isB ? bB : bA;
        int br = isB ? brB : brA;
        int bc = isB ? bcB : bcA;
        float4 val = __ldg(cb4 + s);
        int row = br * 16 + (t >> 2);
        int col = bc * 16 + ((t & 3) << 2);
        reinterpret_cast<float4*>(out + row * ROWS + col)[0] = val;
        int sidx = ROWS * ROWS + bb * 64 + t;
        if (sidx < out_size) out[sidx] = (float)s;
    }
}

} // namespace

extern "C" void kernel_launch(void* const* d_in, const int* in_sizes, int n_in,
                              void* d_out, int out_size) {
    const float* array    = (const float*)d_in[0];
    const float* codebook = (const float*)d_in[1];
    (void)in_sizes; (void)n_in;
    float* out = (float*)d_out;
    viterbi_kernel<<<NCTA, NTH>>>(array, codebook, out, out_size);
}